// round 14
// baseline (speedup 1.0000x reference)
#include <cuda_runtime.h>

#define NTREE 64
#define NPT   3280
#define NINT  1093
#define CD    8
#define GD    8
#define MS    128
#define TPB   256
#define BMS   12            // sBm row stride in floats (48B: 8 bank-groups, f4-aligned)

// smem layout (floats). Beta: stride-8 nodes with intra-node half-swap swizzle.
#define OFF_S     (NINT*8)               // 8744
#define OFF_BM    (OFF_S + 1096)         // 9840
#define OFF_ASP   (OFF_BM + MS*BMS)      // 11376
#define OFF_A2    (OFF_ASP + 3*CD*CD)
#define OFF_PI    (OFF_A2  + 3*CD*CD)
#define OFF_LPI   (OFF_PI  + 3*CD)
#define OFF_RED   (OFF_LPI + 3*CD)
#define OFF_X     (OFF_RED + 8)          // x as uint8, NPT bytes = 820 floats
#define SMEM_FLOATS (OFF_X + (NPT+3)/4)
#define SMEM_BYTES  (SMEM_FLOATS * 4)    // ~49.4 KB -> 4 CTAs/SM

__device__ __forceinline__ void ld8(const float* p, float* v) {
    float4 a = reinterpret_cast<const float4*>(p)[0];
    float4 b = reinterpret_cast<const float4*>(p)[1];
    v[0]=a.x; v[1]=a.y; v[2]=a.z; v[3]=a.w; v[4]=b.x; v[5]=b.y; v[6]=b.z; v[7]=b.w;
}
// swizzled beta access: node n, halves swapped when n&4. No overlap; conflict-free
// for stride-1 and stride-3 node lane patterns.
__device__ __forceinline__ void ld8s(const float* base, int n, float* v) {
    int o = n & 4;
    float4 a = *reinterpret_cast<const float4*>(base + 8*n + o);
    float4 b = *reinterpret_cast<const float4*>(base + 8*n + (o^4));
    v[0]=a.x; v[1]=a.y; v[2]=a.z; v[3]=a.w; v[4]=b.x; v[5]=b.y; v[6]=b.z; v[7]=b.w;
}
__device__ __forceinline__ void st8s(float* base, int n, const float* v) {
    int o = n & 4;
    *reinterpret_cast<float4*>(base + 8*n + o)     = make_float4(v[0],v[1],v[2],v[3]);
    *reinterpret_cast<float4*>(base + 8*n + (o^4)) = make_float4(v[4],v[5],v[6],v[7]);
}
__device__ __forceinline__ float dot8(const float* a, const float* w) {
    float s = a[0]*w[0];
    #pragma unroll
    for (int c = 1; c < CD; c++) s = fmaf(a[c], w[c], s);
    return s;
}

__global__ __launch_bounds__(TPB, 4)
void phtmm_kernel(const float* __restrict__ lamA, const float* __restrict__ lamB,
                  const float* __restrict__ lamPi, const float* __restrict__ lamSP,
                  const void* __restrict__ xraw, float* __restrict__ out)
{
    extern __shared__ __align__(16) float sm[];
    float* sBeta = sm;                 // beta [swizzled]; overwritten by w downward
    float* sS    = sm + OFF_S;         // per-node normalizer S
    float* sBm   = sm + OFF_BM;        // softmax(B)[m][c], row stride BMS
    float* sASP  = sm + OFF_ASP;       // SP*A        [b][cp][c]
    float* sA2   = sm + OFF_A2;        // SP*A*logA
    float* sPi   = sm + OFF_PI;
    float* sLPi  = sm + OFF_LPI;
    float* sRed  = sm + OFF_RED;
    unsigned char* sX = reinterpret_cast<unsigned char*>(sm + OFF_X);

    const int tid  = threadIdx.x;
    const int g    = blockIdx.x;
    const int t    = blockIdx.y;
    const int lane = tid & 31;
    const int wid  = tid >> 5;

    // ---- copy this tree's x into smem as u8 (dtype sniffed once) ----
    {
        const long long* p64 = (const long long*)xraw;
        long long m = p64[0]|p64[1]|p64[2]|p64[3]|p64[4]|p64[5]|p64[6]|p64[7];
        bool is64 = ((unsigned long long)m < (unsigned long long)MS);
        const size_t xo = (size_t)t * NPT;
        if (is64) {
            for (int i = tid; i < NPT; i += TPB)
                sX[i] = (unsigned char)((const long long*)xraw)[xo + i];
        } else {
            for (int i = tid; i < NPT; i += TPB)
                sX[i] = (unsigned char)((const int*)xraw)[xo + i];
        }
    }

    // ---- SP log-softmax (registers) ----
    float lsp[3];
    {
        float v0 = lamSP[g], v1 = lamSP[GD+g], v2 = lamSP[2*GD+g];
        float mx = fmaxf(v0, fmaxf(v1, v2));
        float e0 = __expf(v0-mx), e1 = __expf(v1-mx), e2 = __expf(v2-mx);
        float ld = __logf(e0+e1+e2);
        lsp[0] = (v0-mx)-ld; lsp[1] = (v1-mx)-ld; lsp[2] = (v2-mx)-ld;
    }

    // ---- B softmax: 8 warps; warp w -> column c = w, lanes over m ----
    {
        const int c = wid;
        const float* bb = lamB + (size_t)c * MS * GD + g;
        float v[4]; float mx = -1e30f;
        #pragma unroll
        for (int j = 0; j < 4; j++) { v[j] = bb[(size_t)(lane + 32*j)*GD]; mx = fmaxf(mx, v[j]); }
        #pragma unroll
        for (int o = 16; o >= 1; o >>= 1) mx = fmaxf(mx, __shfl_xor_sync(0xffffffffu, mx, o));
        float e[4]; float den = 0.f;
        #pragma unroll
        for (int j = 0; j < 4; j++) { e[j] = __expf(v[j]-mx); den += e[j]; }
        #pragma unroll
        for (int o = 16; o >= 1; o >>= 1) den += __shfl_xor_sync(0xffffffffu, den, o);
        float inv = __fdividef(1.f, den);
        #pragma unroll
        for (int j = 0; j < 4; j++) sBm[(lane + 32*j)*BMS + c] = e[j]*inv;
    }

    // ---- A softmax over c (fold SP), Pi softmax ----
    if (tid < 24) {
        int b = tid % 3, cp = tid / 3;
        float sp = __expf(lsp[b]);
        float a[CD]; float mx = -1e30f;
        #pragma unroll
        for (int c = 0; c < CD; c++) { a[c] = lamA[((c*CD+cp)*3+b)*GD + g]; mx = fmaxf(mx, a[c]); }
        float den = 0.f;
        #pragma unroll
        for (int c = 0; c < CD; c++) den += __expf(a[c]-mx);
        float ld = __logf(den), inv = __fdividef(1.f, den);
        #pragma unroll
        for (int c = 0; c < CD; c++) {
            float soft = __expf(a[c]-mx) * inv;
            float lg   = (a[c]-mx) - ld;
            sASP[(b*CD+cp)*CD + c] = sp * soft;
            sA2 [(b*CD+cp)*CD + c] = sp * soft * lg;
        }
    } else if (tid < 27) {
        int b = tid - 24;
        float a[CD]; float mx = -1e30f;
        #pragma unroll
        for (int c = 0; c < CD; c++) { a[c] = lamPi[(c*3+b)*GD + g]; mx = fmaxf(mx, a[c]); }
        float den = 0.f;
        #pragma unroll
        for (int c = 0; c < CD; c++) den += __expf(a[c]-mx);
        float ld = __logf(den), inv = __fdividef(1.f, den);
        #pragma unroll
        for (int c = 0; c < CD; c++) {
            sPi [b*CD + c] = __expf(a[c]-mx) * inv;
            sLPi[b*CD + c] = (a[c]-mx) - ld;
        }
    }
    __syncthreads();

    // finish a parent: acc = t_beta -> S, normalized beta (bm preloaded)
    auto finish = [&](int p, float* acc, const float* bm) {
        float s = 0.f;
        #pragma unroll
        for (int c = 0; c < CD; c++) { acc[c] *= bm[c]; s += acc[c]; }
        sS[p] = s;
        float inv = __fdividef(1.f, s);
        #pragma unroll
        for (int c = 0; c < CD; c++) acc[c] *= inv;
        st8s(sBeta, p, acc);
    };

    // ===== upward level 7 (leaf children recomputed on the fly) =====
    for (int p = 364 + tid; p < 1093; p += TPB) {
        int cb = 1093 + 3*(p - 364);
        // early-issue all gathers for this node
        int xv0 = sX[cb], xv1 = sX[cb+1], xv2 = sX[cb+2], xvp = sX[p];
        float bmp[CD]; ld8(sBm + xvp*BMS, bmp);
        float acc[CD] = {0,0,0,0,0,0,0,0};
        int xvs[3] = {xv0, xv1, xv2};
        #pragma unroll
        for (int b = 0; b < 3; b++) {
            float v[CD]; ld8(sBm + xvs[b]*BMS, v);
            float s = 0.f;
            #pragma unroll
            for (int c = 0; c < CD; c++) { v[c] *= sPi[b*CD+c]; s += v[c]; }
            float inv = __fdividef(1.f, s);
            #pragma unroll
            for (int cp = 0; cp < CD; cp++) {
                float av[CD]; ld8(sASP + (b*CD+cp)*CD, av);
                float bcv = v[cp]*inv;
                #pragma unroll
                for (int c = 0; c < CD; c++) acc[c] = fmaf(av[c], bcv, acc[c]);
            }
        }
        finish(p, acc, bmp);
    }
    __syncthreads();

    // ===== upward levels 6..1 =====
    {
        int p0 = 121, p1 = 364;
        #pragma unroll 1
        for (int d = 6; d >= 1; --d) {
            for (int p = p0 + tid; p < p1; p += TPB) {
                int cb = p1 + 3*(p - p0);
                int xvp = sX[p];
                float bmp[CD]; ld8(sBm + xvp*BMS, bmp);   // early gather
                float acc[CD] = {0,0,0,0,0,0,0,0};
                #pragma unroll
                for (int b = 0; b < 3; b++) {
                    float bc[CD]; ld8s(sBeta, cb+b, bc);
                    #pragma unroll
                    for (int cp = 0; cp < CD; cp++) {
                        float av[CD]; ld8(sASP + (b*CD+cp)*CD, av);
                        float bcv = bc[cp];
                        #pragma unroll
                        for (int c = 0; c < CD; c++) acc[c] = fmaf(av[c], bcv, acc[c]);
                    }
                }
                finish(p, acc, bmp);
            }
            p1 = p0; p0 = (p0 - 1) / 3;
            __syncthreads();
        }
    }

    // ===== downward: root =====
    float ell = 0.f;
    if (tid == 0) {
        int xv = sX[0];
        float bm[CD]; ld8(sBm + xv*BMS, bm);
        float bv[CD]; ld8s(sBeta, 0, bv);
        float invS = __fdividef(1.f, sS[0]);
        float w[CD];
        #pragma unroll
        for (int c = 0; c < CD; c++) {
            ell = fmaf(bv[c], bm[c], ell);
            w[c] = bm[c] * invS;            // w = beta/t_beta = bm/S
        }
        st8s(sBeta, 0, w);
    }
    __syncthreads();

    // ===== downward levels 1..6 (children internal), two-pass inner loop =====
    {
        int p0 = 0, p1 = 1;
        #pragma unroll 1
        for (int d = 1; d <= 6; ++d) {
            for (int p = p0 + tid; p < p1; p += TPB) {
                float w[CD]; ld8s(sBeta, p, w);          // parent w
                int cb = p1 + 3*(p - p0);
                #pragma unroll
                for (int b = 0; b < 3; b++) {
                    int ch = cb + b;
                    int xv = sX[ch];                      // early gather
                    float bm[CD]; ld8(sBm + xv*BMS, bm);
                    float bc[CD]; ld8s(sBeta, ch, bc);
                    // pass A: A2 dots (needs only w, bc)
                    float s2 = 0.f;
                    #pragma unroll
                    for (int cp = 0; cp < CD; cp++) {
                        float a2[CD]; ld8(sA2 + (b*CD+cp)*CD, a2);
                        s2 = fmaf(bc[cp], dot8(a2, w), s2);
                    }
                    // pass B: ASP dots -> e, se, ebm, wv
                    float invS = __fdividef(1.f, sS[ch]);
                    float wv[CD]; float se = 0.f, ebm = 0.f;
                    #pragma unroll
                    for (int cp = 0; cp < CD; cp++) {
                        float av[CD]; ld8(sASP + (b*CD+cp)*CD, av);
                        float t1 = dot8(av, w);
                        float e  = bc[cp]*t1;
                        se  += e;
                        ebm  = fmaf(e, bm[cp], ebm);
                        wv[cp] = t1 * bm[cp] * invS;     // w_ch = t1*bm/S
                    }
                    ell += s2 + se*lsp[b] + ebm;
                    st8s(sBeta, ch, wv);                 // overwrite child beta with w
                }
            }
            p0 = p1; p1 = 3*p1 + 1;
            __syncthreads();
        }
    }

    // ===== downward level 7 (leaf children; beta recomputed, + logPi) =====
    for (int p = 364 + tid; p < 1093; p += TPB) {
        float w[CD]; ld8s(sBeta, p, w);
        int cb = 1093 + 3*(p - 364);
        int xv0 = sX[cb], xv1 = sX[cb+1], xv2 = sX[cb+2];   // early gathers
        int xvs[3] = {xv0, xv1, xv2};
        #pragma unroll
        for (int b = 0; b < 3; b++) {
            float bm[CD]; ld8(sBm + xvs[b]*BMS, bm);
            float bc[CD]; float s = 0.f;
            #pragma unroll
            for (int c = 0; c < CD; c++) { bc[c] = sPi[b*CD+c]*bm[c]; s += bc[c]; }
            float inv = __fdividef(1.f, s);
            #pragma unroll
            for (int c = 0; c < CD; c++) bc[c] *= inv;
            // pass A: A2 dots
            float s2 = 0.f;
            #pragma unroll
            for (int cp = 0; cp < CD; cp++) {
                float a2[CD]; ld8(sA2 + (b*CD+cp)*CD, a2);
                s2 = fmaf(bc[cp], dot8(a2, w), s2);
            }
            // pass B: ASP dots
            float lpv[CD]; ld8(sLPi + b*CD, lpv);
            float se = 0.f, ebm = 0.f, elp = 0.f;
            #pragma unroll
            for (int cp = 0; cp < CD; cp++) {
                float av[CD]; ld8(sASP + (b*CD+cp)*CD, av);
                float t1 = dot8(av, w);
                float e  = bc[cp]*t1;
                se  += e;
                ebm  = fmaf(e, bm[cp], ebm);
                elp  = fmaf(e, lpv[cp], elp);
            }
            ell += s2 + se*lsp[b] + ebm + elp;
        }
    }

    // ===== reduce + write =====
    #pragma unroll
    for (int o = 16; o >= 1; o >>= 1) ell += __shfl_down_sync(0xffffffffu, ell, o);
    if (lane == 0) sRed[wid] = ell;
    __syncthreads();
    if (tid == 0) {
        float s = 0.f;
        #pragma unroll
        for (int wI = 0; wI < 8; wI++) s += sRed[wI];
        out[t*GD + g] = -s;
    }
}

extern "C" void kernel_launch(void* const* d_in, const int* in_sizes, int n_in,
                              void* d_out, int out_size) {
    // inputs: 0 lam_A, 1 lam_B, 2 lam_Pi, 3 lam_SP, 4 x, 5 pos, 6 leaves, 7 batch
    cudaFuncSetAttribute(phtmm_kernel, cudaFuncAttributeMaxDynamicSharedMemorySize, SMEM_BYTES);
    dim3 grid(GD, NTREE);   // (g, tree) = 512 CTAs, single wave at 4 CTAs/SM
    phtmm_kernel<<<grid, TPB, SMEM_BYTES>>>((const float*)d_in[0], (const float*)d_in[1],
                                            (const float*)d_in[2], (const float*)d_in[3],
                                            d_in[4], (float*)d_out);
}

// round 15
// speedup vs baseline: 1.0071x; 1.0071x over previous
#include <cuda_runtime.h>

#define NTREE 64
#define NPT   3280
#define NINT  1093
#define CD    8
#define GD    8
#define MS    128
#define TPB   256
#define BMS   12            // sBm row stride in floats (48B -> 8 quad-bank offsets)

// smem layout (floats). Beta: stride-8 nodes with intra-node half-swap swizzle.
#define OFF_S     (NINT*8)               // 8744
#define OFF_BM    (OFF_S + 1096)         // 9840
#define OFF_ASP   (OFF_BM + MS*BMS)      // 11376
#define OFF_A2    (OFF_ASP + 3*CD*CD)
#define OFF_PI    (OFF_A2  + 3*CD*CD)
#define OFF_LPI   (OFF_PI  + 3*CD)
#define OFF_RED   (OFF_LPI + 3*CD)
#define OFF_X     (OFF_RED + 8)          // x as uint8, NPT bytes
#define SMEM_FLOATS (OFF_X + (NPT+3)/4)
#define SMEM_BYTES  (SMEM_FLOATS * 4)    // ~50.5 KB -> 4 CTAs/SM

__device__ __forceinline__ void ld8(const float* p, float* v) {
    float4 a = reinterpret_cast<const float4*>(p)[0];
    float4 b = reinterpret_cast<const float4*>(p)[1];
    v[0]=a.x; v[1]=a.y; v[2]=a.z; v[3]=a.w; v[4]=b.x; v[5]=b.y; v[6]=b.z; v[7]=b.w;
}
// swizzled beta access: node n, halves swapped when n&4. No overlap; conflict-free
// for stride-1 and stride-3 node lane patterns.
__device__ __forceinline__ void ld8s(const float* base, int n, float* v) {
    int o = n & 4;
    float4 a = *reinterpret_cast<const float4*>(base + 8*n + o);
    float4 b = *reinterpret_cast<const float4*>(base + 8*n + (o^4));
    v[0]=a.x; v[1]=a.y; v[2]=a.z; v[3]=a.w; v[4]=b.x; v[5]=b.y; v[6]=b.z; v[7]=b.w;
}
__device__ __forceinline__ void st8s(float* base, int n, const float* v) {
    int o = n & 4;
    *reinterpret_cast<float4*>(base + 8*n + o)     = make_float4(v[0],v[1],v[2],v[3]);
    *reinterpret_cast<float4*>(base + 8*n + (o^4)) = make_float4(v[4],v[5],v[6],v[7]);
}
__device__ __forceinline__ float dot8(const float* a, const float* w) {
    float s = a[0]*w[0];
    #pragma unroll
    for (int c = 1; c < CD; c++) s = fmaf(a[c], w[c], s);
    return s;
}

__global__ __launch_bounds__(TPB, 4)
void phtmm_kernel(const float* __restrict__ lamA, const float* __restrict__ lamB,
                  const float* __restrict__ lamPi, const float* __restrict__ lamSP,
                  const void* __restrict__ xraw, float* __restrict__ out)
{
    extern __shared__ __align__(16) float sm[];
    float* sBeta = sm;                 // beta [swizzled]; overwritten by w downward
    float* sS    = sm + OFF_S;         // per-node normalizer S
    float* sBm   = sm + OFF_BM;        // softmax(B)[m][c], row stride BMS
    float* sASP  = sm + OFF_ASP;       // SP*A        [b][cp][c]
    float* sA2   = sm + OFF_A2;        // SP*A*logA
    float* sPi   = sm + OFF_PI;
    float* sLPi  = sm + OFF_LPI;
    float* sRed  = sm + OFF_RED;
    unsigned char* sX = reinterpret_cast<unsigned char*>(sm + OFF_X);

    const int tid  = threadIdx.x;
    const int g    = blockIdx.x;
    const int t    = blockIdx.y;
    const int lane = tid & 31;
    const int wid  = tid >> 5;

    // ---- stage this tree's x into smem as u8 (dtype sniffed once) ----
    {
        const long long* p64 = (const long long*)xraw;
        long long m = p64[0]|p64[1]|p64[2]|p64[3]|p64[4]|p64[5]|p64[6]|p64[7];
        bool is64 = ((unsigned long long)m < (unsigned long long)MS);
        const size_t xo = (size_t)t * NPT;
        if (is64) {
            for (int i = tid; i < NPT; i += TPB)
                sX[i] = (unsigned char)((const long long*)xraw)[xo + i];
        } else {
            for (int i = tid; i < NPT; i += TPB)
                sX[i] = (unsigned char)((const int*)xraw)[xo + i];
        }
    }

    // ---- SP log-softmax (registers) ----
    float lsp[3];
    {
        float v0 = lamSP[g], v1 = lamSP[GD+g], v2 = lamSP[2*GD+g];
        float mx = fmaxf(v0, fmaxf(v1, v2));
        float e0 = __expf(v0-mx), e1 = __expf(v1-mx), e2 = __expf(v2-mx);
        float ld = __logf(e0+e1+e2);
        lsp[0] = (v0-mx)-ld; lsp[1] = (v1-mx)-ld; lsp[2] = (v2-mx)-ld;
    }

    // ---- B softmax: 8 warps; warp w -> column c = w, lanes over m ----
    {
        const int c = wid;
        const float* bb = lamB + (size_t)c * MS * GD + g;
        float v[4]; float mx = -1e30f;
        #pragma unroll
        for (int j = 0; j < 4; j++) { v[j] = bb[(size_t)(lane + 32*j)*GD]; mx = fmaxf(mx, v[j]); }
        #pragma unroll
        for (int o = 16; o >= 1; o >>= 1) mx = fmaxf(mx, __shfl_xor_sync(0xffffffffu, mx, o));
        float e[4]; float den = 0.f;
        #pragma unroll
        for (int j = 0; j < 4; j++) { e[j] = __expf(v[j]-mx); den += e[j]; }
        #pragma unroll
        for (int o = 16; o >= 1; o >>= 1) den += __shfl_xor_sync(0xffffffffu, den, o);
        float inv = __fdividef(1.f, den);
        #pragma unroll
        for (int j = 0; j < 4; j++) sBm[(lane + 32*j)*BMS + c] = e[j]*inv;
    }

    // ---- A softmax over c (fold SP), Pi softmax ----
    if (tid < 24) {
        int b = tid % 3, cp = tid / 3;
        float sp = __expf(lsp[b]);
        float a[CD]; float mx = -1e30f;
        #pragma unroll
        for (int c = 0; c < CD; c++) { a[c] = lamA[((c*CD+cp)*3+b)*GD + g]; mx = fmaxf(mx, a[c]); }
        float den = 0.f;
        #pragma unroll
        for (int c = 0; c < CD; c++) den += __expf(a[c]-mx);
        float ld = __logf(den), inv = __fdividef(1.f, den);
        #pragma unroll
        for (int c = 0; c < CD; c++) {
            float soft = __expf(a[c]-mx) * inv;
            float lg   = (a[c]-mx) - ld;
            sASP[(b*CD+cp)*CD + c] = sp * soft;
            sA2 [(b*CD+cp)*CD + c] = sp * soft * lg;
        }
    } else if (tid < 27) {
        int b = tid - 24;
        float a[CD]; float mx = -1e30f;
        #pragma unroll
        for (int c = 0; c < CD; c++) { a[c] = lamPi[(c*3+b)*GD + g]; mx = fmaxf(mx, a[c]); }
        float den = 0.f;
        #pragma unroll
        for (int c = 0; c < CD; c++) den += __expf(a[c]-mx);
        float ld = __logf(den), inv = __fdividef(1.f, den);
        #pragma unroll
        for (int c = 0; c < CD; c++) {
            sPi [b*CD + c] = __expf(a[c]-mx) * inv;
            sLPi[b*CD + c] = (a[c]-mx) - ld;
        }
    }
    __syncthreads();

    // finish a parent: acc = t_beta -> S, normalized beta (bm loaded here, as in R6)
    auto finish = [&](int p, float* acc) {
        int xv = sX[p];
        float bm[CD]; ld8(sBm + xv*BMS, bm);
        float s = 0.f;
        #pragma unroll
        for (int c = 0; c < CD; c++) { acc[c] *= bm[c]; s += acc[c]; }
        sS[p] = s;
        float inv = __fdividef(1.f, s);
        #pragma unroll
        for (int c = 0; c < CD; c++) acc[c] *= inv;
        st8s(sBeta, p, acc);
    };

    // ===== upward level 7 (leaf children recomputed on the fly) =====
    for (int p = 364 + tid; p < 1093; p += TPB) {
        float acc[CD] = {0,0,0,0,0,0,0,0};
        int cb = 1093 + 3*(p - 364);
        #pragma unroll
        for (int b = 0; b < 3; b++) {
            int xv = sX[cb + b];
            float v[CD]; ld8(sBm + xv*BMS, v);
            float s = 0.f;
            #pragma unroll
            for (int c = 0; c < CD; c++) { v[c] *= sPi[b*CD+c]; s += v[c]; }
            float inv = __fdividef(1.f, s);
            #pragma unroll
            for (int cp = 0; cp < CD; cp++) {
                float av[CD]; ld8(sASP + (b*CD+cp)*CD, av);
                float bcv = v[cp]*inv;
                #pragma unroll
                for (int c = 0; c < CD; c++) acc[c] = fmaf(av[c], bcv, acc[c]);
            }
        }
        finish(p, acc);
    }
    __syncthreads();

    // ===== upward levels 6..1 =====
    {
        int p0 = 121, p1 = 364;
        #pragma unroll 1
        for (int d = 6; d >= 1; --d) {
            for (int p = p0 + tid; p < p1; p += TPB) {
                float acc[CD] = {0,0,0,0,0,0,0,0};
                int cb = p1 + 3*(p - p0);
                #pragma unroll
                for (int b = 0; b < 3; b++) {
                    float bc[CD]; ld8s(sBeta, cb+b, bc);
                    #pragma unroll
                    for (int cp = 0; cp < CD; cp++) {
                        float av[CD]; ld8(sASP + (b*CD+cp)*CD, av);
                        float bcv = bc[cp];
                        #pragma unroll
                        for (int c = 0; c < CD; c++) acc[c] = fmaf(av[c], bcv, acc[c]);
                    }
                }
                finish(p, acc);
            }
            p1 = p0; p0 = (p0 - 1) / 3;
            __syncthreads();
        }
    }

    // ===== downward: root =====
    float ell = 0.f;
    if (tid == 0) {
        int xv = sX[0];
        float bm[CD]; ld8(sBm + xv*BMS, bm);
        float bv[CD]; ld8s(sBeta, 0, bv);
        float invS = __fdividef(1.f, sS[0]);
        float w[CD];
        #pragma unroll
        for (int c = 0; c < CD; c++) {
            ell = fmaf(bv[c], bm[c], ell);
            w[c] = bm[c] * invS;            // w = beta/t_beta = bm/S
        }
        st8s(sBeta, 0, w);
    }
    __syncthreads();

    // ===== downward levels 1..6 (children internal), two-pass inner loop =====
    {
        int p0 = 0, p1 = 1;
        #pragma unroll 1
        for (int d = 1; d <= 6; ++d) {
            for (int p = p0 + tid; p < p1; p += TPB) {
                float w[CD]; ld8s(sBeta, p, w);          // parent w
                int cb = p1 + 3*(p - p0);
                #pragma unroll
                for (int b = 0; b < 3; b++) {
                    int ch = cb + b;
                    float bc[CD]; ld8s(sBeta, ch, bc);
                    // pass A: A2 dots (needs only w, bc)
                    float s2 = 0.f;
                    #pragma unroll
                    for (int cp = 0; cp < CD; cp++) {
                        float a2[CD]; ld8(sA2 + (b*CD+cp)*CD, a2);
                        s2 = fmaf(bc[cp], dot8(a2, w), s2);
                    }
                    // pass B: ASP dots -> e, se, ebm, wv
                    int xv = sX[ch];
                    float bm[CD]; ld8(sBm + xv*BMS, bm);
                    float invS = __fdividef(1.f, sS[ch]);
                    float wv[CD]; float se = 0.f, ebm = 0.f;
                    #pragma unroll
                    for (int cp = 0; cp < CD; cp++) {
                        float av[CD]; ld8(sASP + (b*CD+cp)*CD, av);
                        float t1 = dot8(av, w);
                        float e  = bc[cp]*t1;
                        se  += e;
                        ebm  = fmaf(e, bm[cp], ebm);
                        wv[cp] = t1 * bm[cp] * invS;     // w_ch = t1*bm/S
                    }
                    ell += s2 + se*lsp[b] + ebm;
                    st8s(sBeta, ch, wv);                 // overwrite child beta with w
                }
            }
            p0 = p1; p1 = 3*p1 + 1;
            __syncthreads();
        }
    }

    // ===== downward level 7 (leaf children; beta recomputed, + logPi) =====
    for (int p = 364 + tid; p < 1093; p += TPB) {
        float w[CD]; ld8s(sBeta, p, w);
        int cb = 1093 + 3*(p - 364);
        #pragma unroll
        for (int b = 0; b < 3; b++) {
            int ch = cb + b;
            int xv = sX[ch];
            float bm[CD]; ld8(sBm + xv*BMS, bm);
            float bc[CD]; float s = 0.f;
            #pragma unroll
            for (int c = 0; c < CD; c++) { bc[c] = sPi[b*CD+c]*bm[c]; s += bc[c]; }
            float inv = __fdividef(1.f, s);
            #pragma unroll
            for (int c = 0; c < CD; c++) bc[c] *= inv;
            // pass A: A2 dots
            float s2 = 0.f;
            #pragma unroll
            for (int cp = 0; cp < CD; cp++) {
                float a2[CD]; ld8(sA2 + (b*CD+cp)*CD, a2);
                s2 = fmaf(bc[cp], dot8(a2, w), s2);
            }
            // pass B: ASP dots
            float lpv[CD]; ld8(sLPi + b*CD, lpv);
            float se = 0.f, ebm = 0.f, elp = 0.f;
            #pragma unroll
            for (int cp = 0; cp < CD; cp++) {
                float av[CD]; ld8(sASP + (b*CD+cp)*CD, av);
                float t1 = dot8(av, w);
                float e  = bc[cp]*t1;
                se  += e;
                ebm  = fmaf(e, bm[cp], ebm);
                elp  = fmaf(e, lpv[cp], elp);
            }
            ell += s2 + se*lsp[b] + ebm + elp;
        }
    }

    // ===== reduce + write =====
    #pragma unroll
    for (int o = 16; o >= 1; o >>= 1) ell += __shfl_down_sync(0xffffffffu, ell, o);
    if (lane == 0) sRed[wid] = ell;
    __syncthreads();
    if (tid == 0) {
        float s = 0.f;
        #pragma unroll
        for (int wI = 0; wI < 8; wI++) s += sRed[wI];
        out[t*GD + g] = -s;
    }
}

extern "C" void kernel_launch(void* const* d_in, const int* in_sizes, int n_in,
                              void* d_out, int out_size) {
    // inputs: 0 lam_A, 1 lam_B, 2 lam_Pi, 3 lam_SP, 4 x, 5 pos, 6 leaves, 7 batch
    cudaFuncSetAttribute(phtmm_kernel, cudaFuncAttributeMaxDynamicSharedMemorySize, SMEM_BYTES);
    dim3 grid(GD, NTREE);   // (g, tree) = 512 CTAs, single wave at 4 CTAs/SM
    phtmm_kernel<<<grid, TPB, SMEM_BYTES>>>((const float*)d_in[0], (const float*)d_in[1],
                                            (const float*)d_in[2], (const float*)d_in[3],
                                            d_in[4], (float*)d_out);
}

// round 17
// speedup vs baseline: 4.4016x; 4.3704x over previous
#include <cuda_runtime.h>

#define NTREE 64
#define NPT   3280
#define NINT  1093
#define CD    8
#define GD    8
#define MS    128
#define TPB   256
#define BMS   12            // sBm row stride in floats (48B -> 8 quad-bank offsets)

// smem layout (floats). Beta: stride-8 nodes with intra-node half-swap swizzle.
#define OFF_S     (NINT*8)               // 8744
#define OFF_BM    (OFF_S + 1096)         // 9840
#define OFF_ASP   (OFF_BM + MS*BMS)      // 11376
#define OFF_A2    (OFF_ASP + 3*CD*CD)
#define OFF_PI    (OFF_A2  + 3*CD*CD)
#define OFF_LPI   (OFF_PI  + 3*CD)
#define OFF_RED   (OFF_LPI + 3*CD)
#define SMEM_FLOATS (OFF_RED + 8)
#define SMEM_BYTES  (SMEM_FLOATS * 4)    // ~47.2 KB -> 4 CTAs/SM

__device__ __forceinline__ int get_x(const void* xr, bool is64, size_t idx) {
    return is64 ? (int)((const long long*)xr)[idx] : ((const int*)xr)[idx];
}
__device__ __forceinline__ void ld8(const float* p, float* v) {
    float4 a = reinterpret_cast<const float4*>(p)[0];
    float4 b = reinterpret_cast<const float4*>(p)[1];
    v[0]=a.x; v[1]=a.y; v[2]=a.z; v[3]=a.w; v[4]=b.x; v[5]=b.y; v[6]=b.z; v[7]=b.w;
}
// swizzled beta access: node n, halves swapped when n&4. No overlap; conflict-free
// for stride-1 and stride-3 node lane patterns.
__device__ __forceinline__ void ld8s(const float* base, int n, float* v) {
    int o = n & 4;
    float4 a = *reinterpret_cast<const float4*>(base + 8*n + o);
    float4 b = *reinterpret_cast<const float4*>(base + 8*n + (o^4));
    v[0]=a.x; v[1]=a.y; v[2]=a.z; v[3]=a.w; v[4]=b.x; v[5]=b.y; v[6]=b.z; v[7]=b.w;
}
__device__ __forceinline__ void st8s(float* base, int n, const float* v) {
    int o = n & 4;
    *reinterpret_cast<float4*>(base + 8*n + o)     = make_float4(v[0],v[1],v[2],v[3]);
    *reinterpret_cast<float4*>(base + 8*n + (o^4)) = make_float4(v[4],v[5],v[6],v[7]);
}
__device__ __forceinline__ float dot8(const float* a, const float* w) {
    float s = a[0]*w[0];
    #pragma unroll
    for (int c = 1; c < CD; c++) s = fmaf(a[c], w[c], s);
    return s;
}

__global__ __launch_bounds__(TPB, 4)
void phtmm_kernel(const float* __restrict__ lamA, const float* __restrict__ lamB,
                  const float* __restrict__ lamPi, const float* __restrict__ lamSP,
                  const void* __restrict__ xraw, float* __restrict__ out)
{
    extern __shared__ __align__(16) float sm[];
    float* sBeta = sm;                 // beta [swizzled]; overwritten by w downward
    float* sS    = sm + OFF_S;         // per-node normalizer S
    float* sBm   = sm + OFF_BM;        // softmax(B)[m][c], row stride BMS
    float* sASP  = sm + OFF_ASP;       // SP*A        [b][cp][c]
    float* sA2   = sm + OFF_A2;        // SP*A*logA
    float* sPi   = sm + OFF_PI;
    float* sLPi  = sm + OFF_LPI;
    float* sRed  = sm + OFF_RED;

    const int tid  = threadIdx.x;
    const int g    = blockIdx.x;
    const int t    = blockIdx.y;
    const int lane = tid & 31;
    const int wid  = tid >> 5;

    bool is64;
    {
        const long long* p = (const long long*)xraw;
        long long m = p[0]|p[1]|p[2]|p[3]|p[4]|p[5]|p[6]|p[7];
        is64 = ((unsigned long long)m < (unsigned long long)MS);
    }

    // ---- SP log-softmax (registers) ----
    float lsp[3];
    {
        float v0 = lamSP[g], v1 = lamSP[GD+g], v2 = lamSP[2*GD+g];
        float mx = fmaxf(v0, fmaxf(v1, v2));
        float e0 = __expf(v0-mx), e1 = __expf(v1-mx), e2 = __expf(v2-mx);
        float ld = __logf(e0+e1+e2);
        lsp[0] = (v0-mx)-ld; lsp[1] = (v1-mx)-ld; lsp[2] = (v2-mx)-ld;
    }

    // ---- B softmax: 8 warps; warp w -> column c = w, lanes over m ----
    {
        const int c = wid;
        const float* bb = lamB + (size_t)c * MS * GD + g;
        float v[4]; float mx = -1e30f;
        #pragma unroll
        for (int j = 0; j < 4; j++) { v[j] = bb[(size_t)(lane + 32*j)*GD]; mx = fmaxf(mx, v[j]); }
        #pragma unroll
        for (int o = 16; o >= 1; o >>= 1) mx = fmaxf(mx, __shfl_xor_sync(0xffffffffu, mx, o));
        float e[4]; float den = 0.f;
        #pragma unroll
        for (int j = 0; j < 4; j++) { e[j] = __expf(v[j]-mx); den += e[j]; }
        #pragma unroll
        for (int o = 16; o >= 1; o >>= 1) den += __shfl_xor_sync(0xffffffffu, den, o);
        float inv = __fdividef(1.f, den);
        #pragma unroll
        for (int j = 0; j < 4; j++) sBm[(lane + 32*j)*BMS + c] = e[j]*inv;
    }

    // ---- A softmax over c (fold SP), Pi softmax ----
    if (tid < 24) {
        int b = tid % 3, cp = tid / 3;
        float sp = __expf(lsp[b]);
        float a[CD]; float mx = -1e30f;
        #pragma unroll
        for (int c = 0; c < CD; c++) { a[c] = lamA[((c*CD+cp)*3+b)*GD + g]; mx = fmaxf(mx, a[c]); }
        float den = 0.f;
        #pragma unroll
        for (int c = 0; c < CD; c++) den += __expf(a[c]-mx);
        float ld = __logf(den), inv = __fdividef(1.f, den);
        #pragma unroll
        for (int c = 0; c < CD; c++) {
            float soft = __expf(a[c]-mx) * inv;
            float lg   = (a[c]-mx) - ld;
            sASP[(b*CD+cp)*CD + c] = sp * soft;
            sA2 [(b*CD+cp)*CD + c] = sp * soft * lg;
        }
    } else if (tid < 27) {
        int b = tid - 24;
        float a[CD]; float mx = -1e30f;
        #pragma unroll
        for (int c = 0; c < CD; c++) { a[c] = lamPi[(c*3+b)*GD + g]; mx = fmaxf(mx, a[c]); }
        float den = 0.f;
        #pragma unroll
        for (int c = 0; c < CD; c++) den += __expf(a[c]-mx);
        float ld = __logf(den), inv = __fdividef(1.f, den);
        #pragma unroll
        for (int c = 0; c < CD; c++) {
            sPi [b*CD + c] = __expf(a[c]-mx) * inv;
            sLPi[b*CD + c] = (a[c]-mx) - ld;
        }
    }
    __syncthreads();

    const size_t xoff = (size_t)t * NPT;

    // finish a parent: acc = t_beta -> S, normalized beta
    auto finish = [&](int p, float* acc) {
        int xv = get_x(xraw, is64, xoff + p);
        float bm[CD]; ld8(sBm + xv*BMS, bm);
        float s = 0.f;
        #pragma unroll
        for (int c = 0; c < CD; c++) { acc[c] *= bm[c]; s += acc[c]; }
        sS[p] = s;
        float inv = __fdividef(1.f, s);
        #pragma unroll
        for (int c = 0; c < CD; c++) acc[c] *= inv;
        st8s(sBeta, p, acc);
    };

    // ===== upward level 7 (leaf children recomputed on the fly) =====
    for (int p = 364 + tid; p < 1093; p += TPB) {
        float acc[CD] = {0,0,0,0,0,0,0,0};
        int cb = 1093 + 3*(p - 364);
        #pragma unroll
        for (int b = 0; b < 3; b++) {
            int xv = get_x(xraw, is64, xoff + cb + b);
            float v[CD]; ld8(sBm + xv*BMS, v);
            float s = 0.f;
            #pragma unroll
            for (int c = 0; c < CD; c++) { v[c] *= sPi[b*CD+c]; s += v[c]; }
            float inv = __fdividef(1.f, s);
            #pragma unroll
            for (int cp = 0; cp < CD; cp++) {
                float av[CD]; ld8(sASP + (b*CD+cp)*CD, av);
                float bcv = v[cp]*inv;
                #pragma unroll
                for (int c = 0; c < CD; c++) acc[c] = fmaf(av[c], bcv, acc[c]);
            }
        }
        finish(p, acc);
    }
    __syncthreads();

    // ===== upward levels 6..1 =====
    {
        int p0 = 121, p1 = 364;
        #pragma unroll 1
        for (int d = 6; d >= 1; --d) {
            for (int p = p0 + tid; p < p1; p += TPB) {
                float acc[CD] = {0,0,0,0,0,0,0,0};
                int cb = p1 + 3*(p - p0);
                #pragma unroll
                for (int b = 0; b < 3; b++) {
                    float bc[CD]; ld8s(sBeta, cb+b, bc);
                    #pragma unroll
                    for (int cp = 0; cp < CD; cp++) {
                        float av[CD]; ld8(sASP + (b*CD+cp)*CD, av);
                        float bcv = bc[cp];
                        #pragma unroll
                        for (int c = 0; c < CD; c++) acc[c] = fmaf(av[c], bcv, acc[c]);
                    }
                }
                finish(p, acc);
            }
            p1 = p0; p0 = (p0 - 1) / 3;
            __syncthreads();
        }
    }

    // ===== downward: root =====
    float ell = 0.f;
    if (tid == 0) {
        int xv = get_x(xraw, is64, xoff);
        float bm[CD]; ld8(sBm + xv*BMS, bm);
        float bv[CD]; ld8s(sBeta, 0, bv);
        float invS = __fdividef(1.f, sS[0]);
        float w[CD];
        #pragma unroll
        for (int c = 0; c < CD; c++) {
            ell = fmaf(bv[c], bm[c], ell);
            w[c] = bm[c] * invS;            // w = beta/t_beta = bm/S
        }
        st8s(sBeta, 0, w);
    }
    __syncthreads();

    // ===== downward levels 1..6 (children internal), two-pass inner loop =====
    {
        int p0 = 0, p1 = 1;
        #pragma unroll 1
        for (int d = 1; d <= 6; ++d) {
            for (int p = p0 + tid; p < p1; p += TPB) {
                float w[CD]; ld8s(sBeta, p, w);          // parent w
                int cb = p1 + 3*(p - p0);
                #pragma unroll
                for (int b = 0; b < 3; b++) {
                    int ch = cb + b;
                    float bc[CD]; ld8s(sBeta, ch, bc);
                    // pass A: A2 dots (needs only w, bc)
                    float s2 = 0.f;
                    #pragma unroll
                    for (int cp = 0; cp < CD; cp++) {
                        float a2[CD]; ld8(sA2 + (b*CD+cp)*CD, a2);
                        s2 = fmaf(bc[cp], dot8(a2, w), s2);
                    }
                    // pass B: ASP dots -> e, se, ebm, wv
                    int xv = get_x(xraw, is64, xoff + ch);
                    float bm[CD]; ld8(sBm + xv*BMS, bm);
                    float invS = __fdividef(1.f, sS[ch]);
                    float wv[CD]; float se = 0.f, ebm = 0.f;
                    #pragma unroll
                    for (int cp = 0; cp < CD; cp++) {
                        float av[CD]; ld8(sASP + (b*CD+cp)*CD, av);
                        float t1 = dot8(av, w);
                        float e  = bc[cp]*t1;
                        se  += e;
                        ebm  = fmaf(e, bm[cp], ebm);
                        wv[cp] = t1 * bm[cp] * invS;     // w_ch = t1*bm/S
                    }
                    ell += s2 + se*lsp[b] + ebm;
                    st8s(sBeta, ch, wv);                 // overwrite child beta with w
                }
            }
            p0 = p1; p1 = 3*p1 + 1;
            __syncthreads();
        }
    }

    // ===== downward level 7 (leaf children; beta recomputed, + logPi) =====
    for (int p = 364 + tid; p < 1093; p += TPB) {
        float w[CD]; ld8s(sBeta, p, w);
        int cb = 1093 + 3*(p - 364);
        #pragma unroll
        for (int b = 0; b < 3; b++) {
            int ch = cb + b;
            int xv = get_x(xraw, is64, xoff + ch);
            float bm[CD]; ld8(sBm + xv*BMS, bm);
            float bc[CD]; float s = 0.f;
            #pragma unroll
            for (int c = 0; c < CD; c++) { bc[c] = sPi[b*CD+c]*bm[c]; s += bc[c]; }
            float inv = __fdividef(1.f, s);
            #pragma unroll
            for (int c = 0; c < CD; c++) bc[c] *= inv;
            // pass A: A2 dots
            float s2 = 0.f;
            #pragma unroll
            for (int cp = 0; cp < CD; cp++) {
                float a2[CD]; ld8(sA2 + (b*CD+cp)*CD, a2);
                s2 = fmaf(bc[cp], dot8(a2, w), s2);
            }
            // pass B: ASP dots
            float lpv[CD]; ld8(sLPi + b*CD, lpv);
            float se = 0.f, ebm = 0.f, elp = 0.f;
            #pragma unroll
            for (int cp = 0; cp < CD; cp++) {
                float av[CD]; ld8(sASP + (b*CD+cp)*CD, av);
                float t1 = dot8(av, w);
                float e  = bc[cp]*t1;
                se  += e;
                ebm  = fmaf(e, bm[cp], ebm);
                elp  = fmaf(e, lpv[cp], elp);
            }
            ell += s2 + se*lsp[b] + ebm + elp;
        }
    }

    // ===== reduce + write =====
    #pragma unroll
    for (int o = 16; o >= 1; o >>= 1) ell += __shfl_down_sync(0xffffffffu, ell, o);
    if (lane == 0) sRed[wid] = ell;
    __syncthreads();
    if (tid == 0) {
        float s = 0.f;
        #pragma unroll
        for (int wI = 0; wI < 8; wI++) s += sRed[wI];
        out[t*GD + g] = -s;
    }
}

extern "C" void kernel_launch(void* const* d_in, const int* in_sizes, int n_in,
                              void* d_out, int out_size) {
    // inputs: 0 lam_A, 1 lam_B, 2 lam_Pi, 3 lam_SP, 4 x, 5 pos, 6 leaves, 7 batch
    cudaFuncSetAttribute(phtmm_kernel, cudaFuncAttributeMaxDynamicSharedMemorySize, SMEM_BYTES);
    dim3 grid(GD, NTREE);   // (g, tree) = 512 CTAs, single wave at 4 CTAs/SM
    phtmm_kernel<<<grid, TPB, SMEM_BYTES>>>((const float*)d_in[0], (const float*)d_in[1],
                                            (const float*)d_in[2], (const float*)d_in[3],
                                            d_in[4], (float*)d_out);
}